// round 1
// baseline (speedup 1.0000x reference)
#include <cuda_runtime.h>
#include <cuda_bf16.h>
#include <math.h>

#define NUM_CLASSES 2
#define BOX_LOSS_SCALE 10.0f

static const int THREADS = 256;
static const int BLOCKS  = 2048;

// Per-block partials: x = sum_nll, y = sum_masked_mse, z = sum_mask, w unused
__device__ float4 g_partials[BLOCKS];

__device__ __forceinline__ float warp_sum(float v) {
    #pragma unroll
    for (int o = 16; o > 0; o >>= 1)
        v += __shfl_down_sync(0xFFFFFFFFu, v, o);
    return v;
}

__global__ __launch_bounds__(THREADS)
void loss_partial_kernel(const float* __restrict__ pred,
                         const int*   __restrict__ tclass,
                         const float* __restrict__ tbox,
                         int n)
{
    float s_nll = 0.0f, s_box = 0.0f, s_msk = 0.0f;

    const int stride = gridDim.x * blockDim.x;
    for (int i = blockIdx.x * blockDim.x + threadIdx.x; i < n; i += stride) {
        // prediction row: 6 floats, 24-byte rows are 8B-aligned -> 3x float2
        const float2* p2 = reinterpret_cast<const float2*>(pred + 6ll * i);
        float2 a = p2[0];   // logits l0, l1
        float2 b = p2[1];   // box pred 0,1
        float2 c = p2[2];   // box pred 2,3
        int   tc = tclass[i];
        float4 tb = reinterpret_cast<const float4*>(tbox)[i];

        // class NLL: lse - chosen
        float l0 = a.x, l1 = a.y;
        float mx = fmaxf(l0, l1);
        float d  = fabsf(l0 - l1);
        float lse = mx + log1pf(__expf(-d));
        float chosen = (tc == 0) ? l0 : l1;
        s_nll += lse - chosen;

        // box MSE (mean over 4) masked by tc != 0
        float e0 = b.x - tb.x;
        float e1 = b.y - tb.y;
        float e2 = c.x - tb.z;
        float e3 = c.y - tb.w;
        float mse = 0.25f * (e0 * e0 + e1 * e1 + e2 * e2 + e3 * e3);
        if (tc != 0) { s_box += mse; s_msk += 1.0f; }
    }

    // block reduction
    __shared__ float sh[3][THREADS / 32];
    s_nll = warp_sum(s_nll);
    s_box = warp_sum(s_box);
    s_msk = warp_sum(s_msk);
    int lane = threadIdx.x & 31;
    int wid  = threadIdx.x >> 5;
    if (lane == 0) { sh[0][wid] = s_nll; sh[1][wid] = s_box; sh[2][wid] = s_msk; }
    __syncthreads();
    if (wid == 0) {
        const int nw = THREADS / 32;
        float v0 = (lane < nw) ? sh[0][lane] : 0.0f;
        float v1 = (lane < nw) ? sh[1][lane] : 0.0f;
        float v2 = (lane < nw) ? sh[2][lane] : 0.0f;
        v0 = warp_sum(v0);
        v1 = warp_sum(v1);
        v2 = warp_sum(v2);
        if (lane == 0)
            g_partials[blockIdx.x] = make_float4(v0, v1, v2, 0.0f);
    }
}

__global__ __launch_bounds__(256)
void loss_final_kernel(float* __restrict__ out, int n)
{
    // 256 threads fold BLOCKS partials in double precision
    double s_nll = 0.0, s_box = 0.0, s_msk = 0.0;
    for (int i = threadIdx.x; i < BLOCKS; i += 256) {
        float4 p = g_partials[i];
        s_nll += (double)p.x;
        s_box += (double)p.y;
        s_msk += (double)p.z;
    }
    __shared__ double sh[3][8];
    // warp reduce in double via shuffle of 64-bit
    #pragma unroll
    for (int o = 16; o > 0; o >>= 1) {
        s_nll += __shfl_down_sync(0xFFFFFFFFu, s_nll, o);
        s_box += __shfl_down_sync(0xFFFFFFFFu, s_box, o);
        s_msk += __shfl_down_sync(0xFFFFFFFFu, s_msk, o);
    }
    int lane = threadIdx.x & 31;
    int wid  = threadIdx.x >> 5;
    if (lane == 0) { sh[0][wid] = s_nll; sh[1][wid] = s_box; sh[2][wid] = s_msk; }
    __syncthreads();
    if (threadIdx.x == 0) {
        double t0 = 0.0, t1 = 0.0, t2 = 0.0;
        #pragma unroll
        for (int w = 0; w < 8; w++) { t0 += sh[0][w]; t1 += sh[1][w]; t2 += sh[2][w]; }
        double class_loss = t0 / (double)n;
        double box_count  = 1e-06 + t2;
        double loss = class_loss + (double)BOX_LOSS_SCALE * t1 / box_count;
        out[0] = (float)loss;
    }
}

extern "C" void kernel_launch(void* const* d_in, const int* in_sizes, int n_in,
                              void* d_out, int out_size)
{
    const float* pred   = (const float*)d_in[0];
    const int*   tclass = (const int*)d_in[1];
    const float* tbox   = (const float*)d_in[2];
    float* out = (float*)d_out;

    int n = in_sizes[1];  // target_class has N elements

    loss_partial_kernel<<<BLOCKS, THREADS>>>(pred, tclass, tbox, n);
    loss_final_kernel<<<1, 256>>>(out, n);
}

// round 4
// speedup vs baseline: 1.2082x; 1.2082x over previous
#include <cuda_runtime.h>
#include <cuda_bf16.h>
#include <math.h>

#define BOX_LOSS_SCALE 10.0f

static const int THREADS = 256;
static const int BLOCKS  = 1184;   // 148 SMs * 8 blocks/SM -> exactly one wave

// Per-block partials: x = sum_nll, y = sum_masked_mse, z = sum_mask
__device__ float4 g_partials[BLOCKS];
__device__ unsigned int g_counter = 0;

__device__ __forceinline__ float warp_sum(float v) {
    #pragma unroll
    for (int o = 16; o > 0; o >>= 1)
        v += __shfl_down_sync(0xFFFFFFFFu, v, o);
    return v;
}

__global__ __launch_bounds__(THREADS)
void loss_fused_kernel(const float* __restrict__ pred,
                       const int*   __restrict__ tclass,
                       const float* __restrict__ tbox,
                       float* __restrict__ out,
                       int n)
{
    float s_nll = 0.0f, s_box = 0.0f, s_msk = 0.0f;

    const int stride = gridDim.x * blockDim.x;
    for (int i = blockIdx.x * blockDim.x + threadIdx.x; i < n; i += stride) {
        // prediction row: 6 floats, 24-byte rows are 8B-aligned -> 3x float2
        const float2* p2 = reinterpret_cast<const float2*>(pred + 6ll * i);
        float2 a = p2[0];   // logits l0, l1
        float2 b = p2[1];   // box pred 0,1
        float2 c = p2[2];   // box pred 2,3
        int   tc = tclass[i];
        float4 tb = reinterpret_cast<const float4*>(tbox)[i];

        // class NLL: lse - chosen logit
        float l0 = a.x, l1 = a.y;
        float mx = fmaxf(l0, l1);
        float d  = fabsf(l0 - l1);
        float lse = mx + log1pf(__expf(-d));
        float chosen = (tc == 0) ? l0 : l1;
        s_nll += lse - chosen;

        // box MSE (mean over 4) masked by tc != 0
        float e0 = b.x - tb.x;
        float e1 = b.y - tb.y;
        float e2 = c.x - tb.z;
        float e3 = c.y - tb.w;
        float mse = 0.25f * (e0 * e0 + e1 * e1 + e2 * e2 + e3 * e3);
        if (tc != 0) { s_box += mse; s_msk += 1.0f; }
    }

    // ---- block reduction ----
    __shared__ float sh[3][THREADS / 32];
    s_nll = warp_sum(s_nll);
    s_box = warp_sum(s_box);
    s_msk = warp_sum(s_msk);
    int lane = threadIdx.x & 31;
    int wid  = threadIdx.x >> 5;
    if (lane == 0) { sh[0][wid] = s_nll; sh[1][wid] = s_box; sh[2][wid] = s_msk; }
    __syncthreads();

    __shared__ bool is_last;
    if (threadIdx.x == 0) {
        const int nw = THREADS / 32;
        float v0 = 0.0f, v1 = 0.0f, v2 = 0.0f;
        #pragma unroll
        for (int w = 0; w < nw; w++) { v0 += sh[0][w]; v1 += sh[1][w]; v2 += sh[2][w]; }
        g_partials[blockIdx.x] = make_float4(v0, v1, v2, 0.0f);
        __threadfence();  // make partial visible before signaling
        unsigned int prev = atomicAdd(&g_counter, 1u);
        is_last = (prev == gridDim.x - 1);
    }
    __syncthreads();

    // ---- last block folds all partials (deterministic order) ----
    if (is_last) {
        double d_nll = 0.0, d_box = 0.0, d_msk = 0.0;
        for (int i = threadIdx.x; i < BLOCKS; i += THREADS) {
            float4 p = g_partials[i];
            d_nll += (double)p.x;
            d_box += (double)p.y;
            d_msk += (double)p.z;
        }
        #pragma unroll
        for (int o = 16; o > 0; o >>= 1) {
            d_nll += __shfl_down_sync(0xFFFFFFFFu, d_nll, o);
            d_box += __shfl_down_sync(0xFFFFFFFFu, d_box, o);
            d_msk += __shfl_down_sync(0xFFFFFFFFu, d_msk, o);
        }
        __shared__ double dsh[3][THREADS / 32];
        if (lane == 0) { dsh[0][wid] = d_nll; dsh[1][wid] = d_box; dsh[2][wid] = d_msk; }
        __syncthreads();
        if (threadIdx.x == 0) {
            double t0 = 0.0, t1 = 0.0, t2 = 0.0;
            #pragma unroll
            for (int w = 0; w < THREADS / 32; w++) { t0 += dsh[0][w]; t1 += dsh[1][w]; t2 += dsh[2][w]; }
            double class_loss = t0 / (double)n;
            double box_count  = 1e-06 + t2;
            out[0] = (float)(class_loss + (double)BOX_LOSS_SCALE * t1 / box_count);
            g_counter = 0;  // reset for next graph replay
        }
    }
}

extern "C" void kernel_launch(void* const* d_in, const int* in_sizes, int n_in,
                              void* d_out, int out_size)
{
    const float* pred   = (const float*)d_in[0];
    const int*   tclass = (const int*)d_in[1];
    const float* tbox   = (const float*)d_in[2];
    float* out = (float*)d_out;

    int n = in_sizes[1];  // target_class element count = N

    loss_fused_kernel<<<BLOCKS, THREADS>>>(pred, tclass, tbox, out, n);
}